// round 3
// baseline (speedup 1.0000x reference)
#include <cuda_runtime.h>

// S4D SSM layer, exact recurrence formulation of the FFT causal conv.
// y[l,b,d] = silu( Re(sum_n p_n s_n[l]) + x[l,b,d]*Dp[d] ),  s = q*s + x.
//
// 3-pass chunked scan, TCHUNK=128.
// Thread-pair split: each thread owns 8 of the 16 states (4 f32x2 packs).
// pass1 uses radix-2 time stepping: s <- q^2 s + (q x0 + x1).

#define NSTATE 16
#define HSTATE 8       // states per thread (half)
#define HPACKS 4       // f32x2 packs per thread
#define TCHUNK 128     // power of two
#define LOG2_TCHUNK 7
#define SCALE_F 0.25f  // sqrt(1/16)

typedef unsigned long long ull;

__device__ __forceinline__ ull pack2(float lo, float hi) {
    ull r; asm("mov.b64 %0, {%1,%2};" : "=l"(r) : "f"(lo), "f"(hi)); return r;
}
__device__ __forceinline__ void unpack2(ull v, float& a, float& b) {
    asm("mov.b64 {%0,%1}, %2;" : "=f"(a), "=f"(b) : "l"(v));
}
__device__ __forceinline__ ull fma2(ull a, ull b, ull c) {
    ull d; asm("fma.rn.f32x2 %0, %1, %2, %3;" : "=l"(d) : "l"(a), "l"(b), "l"(c)); return d;
}
__device__ __forceinline__ ull mul2(ull a, ull b) {
    ull d; asm("mul.rn.f32x2 %0, %1, %2;" : "=l"(d) : "l"(a), "l"(b)); return d;
}

// chunk-boundary states: layout ((c*BSZ + b)*NSTATE + n)*D + d   (coalesced in d)
__device__ float2 g_state[1 << 21];  // 16 MB scratch, static (allocation-free)

// q_n for one state (bilinear transform)
__device__ __forceinline__ void q_of(float dt, float lar, float aim,
                                     float& qr, float& qi)
{
    float zr = -0.5f * dt * __expf(lar);
    float zi =  0.5f * dt * aim;
    float omz = 1.0f - zr;
    float inv = __fdividef(1.0f, omz * omz + zi * zi);
    qr = (1.0f - zr * zr - zi * zi) * inv;
    qi = 2.0f * zi * inv;
}

// ---------------------------------------------------------------------------
// pass1: local scan per chunk with zero init, radix-2 steps, store end states.
// thread t: d = blockIdx.x*64 + (t>>1), owns states n = 8*(t&1) .. +7
// ---------------------------------------------------------------------------
__global__ void __launch_bounds__(128) s4d_pass1(
    const float* __restrict__ x, const float* __restrict__ log_dt,
    const float* __restrict__ log_A_real, const float* __restrict__ A_imag,
    int L, int D)
{
    int tid = threadIdx.x;
    int h   = tid & 1;
    int d   = blockIdx.x * 64 + (tid >> 1);
    int b   = blockIdx.y;
    int c   = blockIdx.z;
    int BSZ = gridDim.y;

    float dt = __expf(log_dt[d]);
    int nbase = d * NSTATE + h * HSTATE;

    ull Qr[HPACKS], nQi[HPACKS], Q2r[HPACKS], Q2i[HPACKS], nQ2i[HPACKS];
    ull Sr[HPACKS], Sm[HPACKS];
#pragma unroll
    for (int j = 0; j < HPACKS; j++) {
        float qr0, qi0, qr1, qi1;
        q_of(dt, log_A_real[nbase + 2*j],     A_imag[nbase + 2*j],     qr0, qi0);
        q_of(dt, log_A_real[nbase + 2*j + 1], A_imag[nbase + 2*j + 1], qr1, qi1);
        float q2r0 = qr0*qr0 - qi0*qi0, q2i0 = 2.0f*qr0*qi0;
        float q2r1 = qr1*qr1 - qi1*qi1, q2i1 = 2.0f*qr1*qi1;
        Qr[j]   = pack2(qr0, qr1);
        nQi[j]  = pack2(-qi0, -qi1);
        Q2r[j]  = pack2(q2r0, q2r1);
        Q2i[j]  = pack2(q2i0, q2i1);
        nQ2i[j] = pack2(-q2i0, -q2i1);
        Sr[j] = 0ull; Sm[j] = 0ull;   // Sm holds m = -si
    }

    long long xstride = (long long)BSZ * D;
    const float* xp = x + ((long long)(c * TCHUNK) * BSZ + b) * D + d;

    const int ITERS = TCHUNK / 4;
    float x0 = xp[0];
    float x1 = xp[xstride];
    float x2 = xp[2 * xstride];
    float x3 = xp[3 * xstride];

    for (int it = 0; it < ITERS; it++) {
        // guarded prefetch of next group
        const float* xpn = (it + 1 < ITERS) ? (xp + 4 * xstride) : xp;
        float n0 = xpn[0];
        float n1 = xpn[xstride];
        float n2 = xpn[2 * xstride];
        float n3 = xpn[3 * xstride];
        xp = xpn;

        // two radix-2 steps: (x0,x1) then (x2,x3)
#pragma unroll
        for (int u = 0; u < 2; u++) {
            float a = (u == 0) ? x0 : x2;
            float bb = (u == 0) ? x1 : x3;
            ull X0 = pack2(a, a);
            ull X1 = pack2(bb, bb);
#pragma unroll
            for (int j = 0; j < HPACKS; j++) {
                ull Vr = fma2(Qr[j], X0, X1);      // qr*x0 + x1
                ull Vm = mul2(nQi[j], X0);         // -qi*x0
                ull t1 = fma2(Q2i[j], Sm[j], Vr);
                ull t2 = fma2(Q2r[j], Sm[j], Vm);
                ull so = Sr[j];
                Sr[j] = fma2(Q2r[j], so, t1);
                Sm[j] = fma2(nQ2i[j], so, t2);
            }
        }
        x0 = n0; x1 = n1; x2 = n2; x3 = n3;
    }

    float2* st = g_state + (((long long)c * BSZ + b) * NSTATE) * D + d;
#pragma unroll
    for (int j = 0; j < HPACKS; j++) {
        float r0, r1, m0, m1;
        unpack2(Sr[j], r0, r1); unpack2(Sm[j], m0, m1);
        int n = h * HSTATE + 2 * j;
        st[(long long)n * D]       = make_float2(r0, -m0);
        st[(long long)(n + 1) * D] = make_float2(r1, -m1);
    }
}

// ---------------------------------------------------------------------------
// pass2: carry propagation across chunks with q^TCHUNK
// ---------------------------------------------------------------------------
__global__ void s4d_pass2(
    const float* __restrict__ log_dt, const float* __restrict__ log_A_real,
    const float* __restrict__ A_imag, int D, int BSZ, int NCH)
{
    int id = blockIdx.x * blockDim.x + threadIdx.x;
    int total = BSZ * NSTATE * D;
    if (id >= total) return;
    int d = id % D;
    int n = (id / D) % NSTATE;
    int b = id / (D * NSTATE);

    float dt = __expf(log_dt[d]);
    float qr, qi;
    q_of(dt, log_A_real[d * NSTATE + n], A_imag[d * NSTATE + n], qr, qi);

#pragma unroll
    for (int i = 0; i < LOG2_TCHUNK; i++) {
        float nr = qr * qr - qi * qi;
        float ni = 2.0f * qr * qi;
        qr = nr; qi = ni;
    }

    long long base    = ((long long)b * NSTATE + n) * D + d;
    long long cstride = (long long)BSZ * NSTATE * D;
    float2 s = g_state[base];
    for (int c = 1; c < NCH; c++) {
        float2 t = g_state[base + (long long)c * cstride];
        float nr = qr * s.x - qi * s.y + t.x;
        float ni = qr * s.y + qi * s.x + t.y;
        s.x = nr; s.y = ni;
        g_state[base + (long long)c * cstride] = s;
    }
}

// ---------------------------------------------------------------------------
// pass3: scan with true init + projection + residual + silu.
// Thread pair (tid, tid^1) covers one d; partial y summed via shfl_xor.
// ---------------------------------------------------------------------------
__global__ void __launch_bounds__(128) s4d_pass3(
    const float* __restrict__ x, const float* __restrict__ log_dt,
    const float* __restrict__ log_A_real, const float* __restrict__ A_imag,
    const float* __restrict__ Bparam, const float* __restrict__ Cparam,
    const float* __restrict__ Dparam, float* __restrict__ out,
    int L, int D)
{
    int tid = threadIdx.x;
    int h   = tid & 1;
    int d   = blockIdx.x * 64 + (tid >> 1);
    int b   = blockIdx.y;
    int c   = blockIdx.z;
    int BSZ = gridDim.y;

    float dt = __expf(log_dt[d]);
    int nbase = d * NSTATE + h * HSTATE;

    ull Qr[HPACKS], Qi[HPACKS], nQi[HPACKS], Pr[HPACKS], Pi[HPACKS];
    ull Sr[HPACKS], Sm[HPACKS];
#pragma unroll
    for (int j = 0; j < HPACKS; j++) {
        float prj[2], pij[2], qrj[2], qij[2];
#pragma unroll
        for (int k = 0; k < 2; k++) {
            int n = nbase + 2 * j + k;
            float zr = -0.5f * dt * __expf(log_A_real[n]);
            float zi =  0.5f * dt * A_imag[n];
            float omz = 1.0f - zr;
            float inv = __fdividef(1.0f, omz * omz + zi * zi);
            qrj[k] = (1.0f - zr * zr - zi * zi) * inv;
            qij[k] = 2.0f * zi * inv;
            float Br = Bparam[n * 2 + 0];
            float Bi = Bparam[n * 2 + 1];
            float Cr = Cparam[n * 2 + 0];
            float Ci = Cparam[n * 2 + 1];
            float ccr = Br * Cr - Bi * Ci;
            float cci = Br * Ci + Bi * Cr;
            float w = dt * SCALE_F * inv;
            prj[k] = w * (ccr * omz - cci * zi);
            pij[k] = w * (ccr * zi + cci * omz);
        }
        Qr[j]  = pack2(qrj[0], qrj[1]);
        Qi[j]  = pack2(qij[0], qij[1]);
        nQi[j] = pack2(-qij[0], -qij[1]);
        Pr[j]  = pack2(prj[0], prj[1]);
        Pi[j]  = pack2(pij[0], pij[1]);
        Sr[j] = 0ull; Sm[j] = 0ull;
    }

    // true incoming state = end state of chunk c-1
    if (c > 0) {
        const float2* st = g_state + (((long long)(c - 1) * BSZ + b) * NSTATE) * D + d;
#pragma unroll
        for (int j = 0; j < HPACKS; j++) {
            int n = h * HSTATE + 2 * j;
            float2 v0 = st[(long long)n * D];
            float2 v1 = st[(long long)(n + 1) * D];
            Sr[j] = pack2(v0.x, v1.x);
            Sm[j] = pack2(-v0.y, -v1.y);  // m = -si
        }
    }

    float dpar = Dparam[d];
    long long xstride = (long long)BSZ * D;
    const float* xp = x + ((long long)(c * TCHUNK) * BSZ + b) * D + d;
    float* op = out + ((long long)(c * TCHUNK) * BSZ + b) * D + d;

    const int ITERS = TCHUNK / 2;
    float x0 = xp[0];
    float x1 = xp[xstride];

    for (int it = 0; it < ITERS; it++) {
        const float* xpn = (it + 1 < ITERS) ? (xp + 2 * xstride) : xp;
        float n0 = xpn[0];
        float n1 = xpn[xstride];
        xp = xpn;

#pragma unroll
        for (int u = 0; u < 2; u++) {
            float xv = (u == 0) ? x0 : x1;
            ull X2 = pack2(xv, xv);
            ull acc0 = 0ull, acc1 = 0ull;
#pragma unroll
            for (int j = 0; j < HPACKS; j++) {
                ull t   = fma2(Qi[j], Sm[j], X2);
                ull nsr = fma2(Qr[j], Sr[j], t);
                ull nm  = fma2(nQi[j], Sr[j], mul2(Qr[j], Sm[j]));
                Sr[j] = nsr; Sm[j] = nm;
                if (j & 1) {
                    acc1 = fma2(Pi[j], nm, acc1);
                    acc1 = fma2(Pr[j], nsr, acc1);
                } else {
                    acc0 = fma2(Pi[j], nm, acc0);
                    acc0 = fma2(Pr[j], nsr, acc0);
                }
            }
            float a0, a1, b0, b1;
            unpack2(acc0, a0, a1); unpack2(acc1, b0, b1);
            float ypart = (a0 + a1) + (b0 + b1);
            float y = ypart + __shfl_xor_sync(0xffffffffu, ypart, 1);
            float z = fmaf(xv, dpar, y);
            float sg = __fdividef(1.0f, 1.0f + __expf(-z));
            if (h == 0)
                op[(long long)u * xstride] = z * sg;
        }
        op += 2 * xstride;
        x0 = n0; x1 = n1;
    }
}

extern "C" void kernel_launch(void* const* d_in, const int* in_sizes, int n_in,
                              void* d_out, int out_size)
{
    const float* x      = (const float*)d_in[0];
    const float* log_dt = (const float*)d_in[1];
    const float* lar    = (const float*)d_in[2];
    const float* aim    = (const float*)d_in[3];
    const float* Bp     = (const float*)d_in[4];
    const float* Cp     = (const float*)d_in[5];
    const float* Dp     = (const float*)d_in[6];
    float* out = (float*)d_out;

    int D   = in_sizes[6];              // D_param has D elements
    int BSZ = 4;                        // batch (fixed by problem)
    int L   = in_sizes[0] / (BSZ * D);
    int NCH = (L + TCHUNK - 1) / TCHUNK;

    dim3 blk(128);                      // 64 d per block, 2 threads per d
    dim3 grd(D / 64, BSZ, NCH);

    s4d_pass1<<<grd, blk>>>(x, log_dt, lar, aim, L, D);

    int total2 = BSZ * NSTATE * D;
    s4d_pass2<<<(total2 + 255) / 256, 256>>>(log_dt, lar, aim, D, BSZ, NCH);

    s4d_pass3<<<grd, blk>>>(x, log_dt, lar, aim, Bp, Cp, Dp, out, L, D);
}

// round 4
// speedup vs baseline: 1.0348x; 1.0348x over previous
#include <cuda_runtime.h>

// S4D SSM layer, exact recurrence formulation of the FFT causal conv.
//
// pass1: complex local scan per chunk (zero init) -> end states (1 thread/d, 8 packs)
// pass2: carry propagation across chunks with q^TCHUNK
// pass3: second-order REAL recurrence on u = Re(p*s):
//        u_i = a u_{i-1} + b u_{i-2} + pr*x_i - g*x_{i-1},
//        a = 2 Re(q), b = -|q|^2, g = Re(p conj(q)).

#define NSTATE 16
#define PACKS  8       // 2 states per f32x2 pack
#define TCHUNK 128     // power of two
#define LOG2_TCHUNK 7
#define SCALE_F 0.25f  // sqrt(1/16)

typedef unsigned long long ull;

__device__ __forceinline__ ull pack2(float lo, float hi) {
    ull r; asm("mov.b64 %0, {%1,%2};" : "=l"(r) : "f"(lo), "f"(hi)); return r;
}
__device__ __forceinline__ void unpack2(ull v, float& a, float& b) {
    asm("mov.b64 {%0,%1}, %2;" : "=f"(a), "=f"(b) : "l"(v));
}
__device__ __forceinline__ ull fma2(ull a, ull b, ull c) {
    ull d; asm("fma.rn.f32x2 %0, %1, %2, %3;" : "=l"(d) : "l"(a), "l"(b), "l"(c)); return d;
}
__device__ __forceinline__ ull mul2(ull a, ull b) {
    ull d; asm("mul.rn.f32x2 %0, %1, %2;" : "=l"(d) : "l"(a), "l"(b)); return d;
}
__device__ __forceinline__ ull add2(ull a, ull b) {
    ull d; asm("add.rn.f32x2 %0, %1, %2;" : "=l"(d) : "l"(a), "l"(b)); return d;
}

// chunk-boundary states: layout ((c*BSZ + b)*NSTATE + n)*D + d   (coalesced in d)
__device__ float2 g_state[1 << 21];  // 16 MB scratch, static (allocation-free)

// q_n for one state (bilinear transform)
__device__ __forceinline__ void q_of(float dt, float lar, float aim,
                                     float& qr, float& qi)
{
    float zr = -0.5f * dt * __expf(lar);
    float zi =  0.5f * dt * aim;
    float omz = 1.0f - zr;
    float inv = __fdividef(1.0f, omz * omz + zi * zi);
    qr = (1.0f - zr * zr - zi * zi) * inv;
    qi = 2.0f * zi * inv;
}

// ---------------------------------------------------------------------------
// pass1: complex local scan, 1 thread per d, 8 packs, x4 unroll + prefetch.
// ---------------------------------------------------------------------------
__global__ void __launch_bounds__(128) s4d_pass1(
    const float* __restrict__ x, const float* __restrict__ log_dt,
    const float* __restrict__ log_A_real, const float* __restrict__ A_imag,
    int L, int D)
{
    int d = blockIdx.x * blockDim.x + threadIdx.x;
    if (d >= D) return;
    int b = blockIdx.y;
    int c = blockIdx.z;
    int BSZ = gridDim.y;

    float dt = __expf(log_dt[d]);

    ull Qr[PACKS], Qi[PACKS], nQi[PACKS], Sr[PACKS], Sm[PACKS];
#pragma unroll
    for (int j = 0; j < PACKS; j++) {
        float qr0, qi0, qr1, qi1;
        q_of(dt, log_A_real[d*NSTATE + 2*j],   A_imag[d*NSTATE + 2*j],   qr0, qi0);
        q_of(dt, log_A_real[d*NSTATE + 2*j+1], A_imag[d*NSTATE + 2*j+1], qr1, qi1);
        Qr[j]  = pack2(qr0, qr1);
        Qi[j]  = pack2(qi0, qi1);
        nQi[j] = pack2(-qi0, -qi1);
        Sr[j] = 0ull; Sm[j] = 0ull;   // Sm holds m = -si
    }

    long long xstride = (long long)BSZ * D;
    const float* xp = x + ((long long)(c * TCHUNK) * BSZ + b) * D + d;

    const int ITERS = TCHUNK / 4;
    float x0 = xp[0];
    float x1 = xp[xstride];
    float x2 = xp[2 * xstride];
    float x3 = xp[3 * xstride];

    for (int it = 0; it < ITERS; it++) {
        const float* xpn = (it + 1 < ITERS) ? (xp + 4 * xstride) : xp;
        float n0 = xpn[0];
        float n1 = xpn[xstride];
        float n2 = xpn[2 * xstride];
        float n3 = xpn[3 * xstride];
        xp = xpn;

#pragma unroll
        for (int u = 0; u < 4; u++) {
            float xv = (u == 0) ? x0 : (u == 1) ? x1 : (u == 2) ? x2 : x3;
            ull X2 = pack2(xv, xv);
#pragma unroll
            for (int j = 0; j < PACKS; j++) {
                // sr' = qr*sr + qi*m + x   (m = -si)
                ull t   = fma2(Qi[j], Sm[j], X2);
                ull nsr = fma2(Qr[j], Sr[j], t);
                // m'  = -qi*sr + qr*m
                ull nm  = fma2(nQi[j], Sr[j], mul2(Qr[j], Sm[j]));
                Sr[j] = nsr; Sm[j] = nm;
            }
        }
        x0 = n0; x1 = n1; x2 = n2; x3 = n3;
    }

    float2* st = g_state + (((long long)c * BSZ + b) * NSTATE) * D + d;
#pragma unroll
    for (int j = 0; j < PACKS; j++) {
        float r0, r1, m0, m1;
        unpack2(Sr[j], r0, r1); unpack2(Sm[j], m0, m1);
        st[(long long)(2*j    ) * D] = make_float2(r0, -m0);  // (sr, si)
        st[(long long)(2*j + 1) * D] = make_float2(r1, -m1);
    }
}

// ---------------------------------------------------------------------------
// pass2: carry propagation across chunks with q^TCHUNK
// ---------------------------------------------------------------------------
__global__ void s4d_pass2(
    const float* __restrict__ log_dt, const float* __restrict__ log_A_real,
    const float* __restrict__ A_imag, int D, int BSZ, int NCH)
{
    int id = blockIdx.x * blockDim.x + threadIdx.x;
    int total = BSZ * NSTATE * D;
    if (id >= total) return;
    int d = id % D;
    int n = (id / D) % NSTATE;
    int b = id / (D * NSTATE);

    float dt = __expf(log_dt[d]);
    float qr, qi;
    q_of(dt, log_A_real[d * NSTATE + n], A_imag[d * NSTATE + n], qr, qi);

#pragma unroll
    for (int i = 0; i < LOG2_TCHUNK; i++) {
        float nr = qr * qr - qi * qi;
        float ni = 2.0f * qr * qi;
        qr = nr; qi = ni;
    }

    long long base    = ((long long)b * NSTATE + n) * D + d;
    long long cstride = (long long)BSZ * NSTATE * D;
    float2 s = g_state[base];
    for (int c = 1; c < NCH; c++) {
        float2 t = g_state[base + (long long)c * cstride];
        float nr = qr * s.x - qi * s.y + t.x;
        float ni = qr * s.y + qi * s.x + t.y;
        s.x = nr; s.y = ni;
        g_state[base + (long long)c * cstride] = s;
    }
}

// ---------------------------------------------------------------------------
// pass3: 2nd-order real recurrence on u = Re(p*s), + residual + silu.
// ---------------------------------------------------------------------------
__device__ __forceinline__ float silu_of(float z) {
    float sg = __fdividef(1.0f, 1.0f + __expf(-z));
    return z * sg;
}

__global__ void __launch_bounds__(128) s4d_pass3(
    const float* __restrict__ x, const float* __restrict__ log_dt,
    const float* __restrict__ log_A_real, const float* __restrict__ A_imag,
    const float* __restrict__ Bparam, const float* __restrict__ Cparam,
    const float* __restrict__ Dparam, float* __restrict__ out,
    int L, int D)
{
    int d = blockIdx.x * blockDim.x + threadIdx.x;
    if (d >= D) return;
    int b = blockIdx.y;
    int c = blockIdx.z;
    int BSZ = gridDim.y;

    float dt = __expf(log_dt[d]);
    long long xstride = (long long)BSZ * D;
    const float* xp = x + ((long long)(c * TCHUNK) * BSZ + b) * D + d;
    float* op = out + ((long long)(c * TCHUNK) * BSZ + b) * D + d;
    float dpar = Dparam[d];

    float xs0 = xp[0];

    ull A[PACKS], Bc[PACKS], Pr[PACKS], nG[PACKS], V[PACKS], V1[PACKS];
    float y0 = 0.0f;

#pragma unroll
    for (int j = 0; j < PACKS; j++) {
        float u0[2], um1[2], aa[2], bb[2], prr[2], gg[2];
#pragma unroll
        for (int k = 0; k < 2; k++) {
            int n = d * NSTATE + 2 * j + k;
            float zr = -0.5f * dt * __expf(log_A_real[n]);
            float zi =  0.5f * dt * A_imag[n];
            float omz = 1.0f - zr;
            float inv = __fdividef(1.0f, omz * omz + zi * zi);
            float qr = (1.0f - zr * zr - zi * zi) * inv;
            float qi = 2.0f * zi * inv;
            float Br = Bparam[n * 2 + 0];
            float Bi = Bparam[n * 2 + 1];
            float Cr = Cparam[n * 2 + 0];
            float Ci = Cparam[n * 2 + 1];
            float ccr = Br * Cr - Bi * Ci;
            float cci = Br * Ci + Bi * Cr;
            float w = dt * SCALE_F * inv;
            float pr = w * (ccr * omz - cci * zi);
            float pi = w * (ccr * zi + cci * omz);

            aa[k]  = 2.0f * qr;
            bb[k]  = -(qr * qr + qi * qi);
            prr[k] = pr;
            gg[k]  = -(pr * qr + pi * qi);      // -g

            // carry state s_c (complex) from pass2 (chunk c-1 end)
            float sr = 0.0f, si = 0.0f;
            if (c > 0) {
                float2 v = g_state[(((long long)(c-1) * BSZ + b) * NSTATE + 2*j + k) * D + d];
                sr = v.x; si = v.y;
            }
            // u_{-1} = Re(p s_c);  u_0 = Re(p q s_c) + pr*xs0
            um1[k] = pr * sr - pi * si;
            float pqr = pr * qr - pi * qi;
            float pqi = pr * qi + pi * qr;
            u0[k]  = pqr * sr - pqi * si + pr * xs0;
            y0 += u0[k];
        }
        A[j]  = pack2(aa[0], aa[1]);
        Bc[j] = pack2(bb[0], bb[1]);
        Pr[j] = pack2(prr[0], prr[1]);
        nG[j] = pack2(gg[0], gg[1]);
        V[j]  = pack2(u0[0], u0[1]);
        V1[j] = pack2(um1[0], um1[1]);
    }

    // output index 0
    op[0] = silu_of(fmaf(xs0, dpar, y0));

    // ---- step macro: u_i = A*V + Bc*V1 + Pr*xc - g*xm1; output at index i ----
#define STEP_OUT(XC, XM1, OPTR)                                              \
    {                                                                        \
        ull Xc = pack2((XC), (XC));                                          \
        ull Xm = pack2((XM1), (XM1));                                        \
        ull nv[PACKS];                                                       \
        _Pragma("unroll")                                                    \
        for (int j = 0; j < PACKS; j++) {                                    \
            ull w  = fma2(Pr[j], Xc, mul2(nG[j], Xm));                       \
            ull t  = fma2(Bc[j], V1[j], w);                                  \
            nv[j]  = fma2(A[j], V[j], t);                                    \
            V1[j] = V[j]; V[j] = nv[j];                                      \
        }                                                                    \
        ull s01 = add2(nv[0], nv[1]);                                        \
        ull s23 = add2(nv[2], nv[3]);                                        \
        ull s45 = add2(nv[4], nv[5]);                                        \
        ull s67 = add2(nv[6], nv[7]);                                        \
        ull s03 = add2(s01, s23);                                            \
        ull s47 = add2(s45, s67);                                            \
        ull sA  = add2(s03, s47);                                            \
        float ylo, yhi; unpack2(sA, ylo, yhi);                               \
        float yv = ylo + yhi;                                                \
        *(OPTR) = silu_of(fmaf((XC), dpar, yv));                             \
    }

    // i = 1 (single step)
    float xm1 = xs0;
    float xc  = xp[xstride];
    STEP_OUT(xc, xm1, op + xstride);
    xm1 = xc;

    // i = 2..TCHUNK-1 in pairs (63 iterations)
    float xa = xp[2 * xstride];
    float xb = xp[3 * xstride];
    const float* xpf = xp + 2 * xstride;   // points at xs[i] for current pair
    float* opc = op + 2 * xstride;

    const int PAIRS = (TCHUNK - 2) / 2;    // 63
    for (int it = 0; it < PAIRS; it++) {
        const float* xpn = (it + 1 < PAIRS) ? (xpf + 2 * xstride) : xpf;
        float na = xpn[0];
        float nb = xpn[xstride];
        xpf = xpn;

        STEP_OUT(xa, xm1, opc);
        STEP_OUT(xb, xa, opc + xstride);
        xm1 = xb;
        xa = na; xb = nb;
        opc += 2 * xstride;
    }
#undef STEP_OUT
}

extern "C" void kernel_launch(void* const* d_in, const int* in_sizes, int n_in,
                              void* d_out, int out_size)
{
    const float* x      = (const float*)d_in[0];
    const float* log_dt = (const float*)d_in[1];
    const float* lar    = (const float*)d_in[2];
    const float* aim    = (const float*)d_in[3];
    const float* Bp     = (const float*)d_in[4];
    const float* Cp     = (const float*)d_in[5];
    const float* Dp     = (const float*)d_in[6];
    float* out = (float*)d_out;

    int D   = in_sizes[6];              // D_param has D elements
    int BSZ = 4;                        // batch (fixed by problem)
    int L   = in_sizes[0] / (BSZ * D);
    int NCH = (L + TCHUNK - 1) / TCHUNK;

    dim3 blk(128);
    dim3 grd((D + 127) / 128, BSZ, NCH);

    s4d_pass1<<<grd, blk>>>(x, log_dt, lar, aim, L, D);

    int total2 = BSZ * NSTATE * D;
    s4d_pass2<<<(total2 + 255) / 256, 256>>>(log_dt, lar, aim, D, BSZ, NCH);

    s4d_pass3<<<grd, blk>>>(x, log_dt, lar, aim, Bp, Cp, Dp, out, L, D);
}

// round 5
// speedup vs baseline: 1.0921x; 1.0553x over previous
#include <cuda_runtime.h>

// S4D SSM layer, recurrence formulation of the FFT causal conv.
// Shapes hardcoded per problem: L=4096, B=4, D=1024, N=16.
//
// pass1: complex local scan per chunk (zero init), batch-merged 2x
// pass2: carry propagation across chunks with q^TCHUNK (complex)
// pass3: 2nd-order REAL recurrence on u = Re(p*s), batch-merged 2x:
//        u_i = a u_{i-1} + b u_{i-2} + pr*x_i - g*x_{i-1}

#define NSTATE 16
#define PACKS  8
#define TCHUNK 128
#define LOG2_TCHUNK 7
#define NCH    32          // L / TCHUNK
#define D_DIM  1024
#define B_SZ   4
#define XS     (B_SZ * D_DIM)   // float stride per timestep = 4096
#define SCALE_F 0.25f

typedef unsigned long long ull;

__device__ __forceinline__ ull pack2(float lo, float hi) {
    ull r; asm("mov.b64 %0, {%1,%2};" : "=l"(r) : "f"(lo), "f"(hi)); return r;
}
__device__ __forceinline__ void unpack2(ull v, float& a, float& b) {
    asm("mov.b64 {%0,%1}, %2;" : "=f"(a), "=f"(b) : "l"(v));
}
__device__ __forceinline__ ull fma2(ull a, ull b, ull c) {
    ull d; asm("fma.rn.f32x2 %0, %1, %2, %3;" : "=l"(d) : "l"(a), "l"(b), "l"(c)); return d;
}
__device__ __forceinline__ ull mul2(ull a, ull b) {
    ull d; asm("mul.rn.f32x2 %0, %1, %2;" : "=l"(d) : "l"(a), "l"(b)); return d;
}
__device__ __forceinline__ ull add2(ull a, ull b) {
    ull d; asm("add.rn.f32x2 %0, %1, %2;" : "=l"(d) : "l"(a), "l"(b)); return d;
}

// chunk-boundary states: ((c*B + b)*NSTATE + n)*D + d  — 2M float2 = 16MB
__device__ float2 g_state[1 << 21];

__device__ __forceinline__ void q_of(float dt, float lar, float aim,
                                     float& qr, float& qi)
{
    float zr = -0.5f * dt * __expf(lar);
    float zi =  0.5f * dt * aim;
    float omz = 1.0f - zr;
    float inv = __fdividef(1.0f, omz * omz + zi * zi);
    qr = (1.0f - zr * zr - zi * zi) * inv;
    qi = 2.0f * zi * inv;
}

__device__ __forceinline__ float silu_of(float z) {
    float sg = __fdividef(1.0f, 1.0f + __expf(-z));
    return z * sg;
}

// one complex recurrence step over all packs (Sm = -Im(s))
__device__ __forceinline__ void cstep(const ull* Qr, const ull* Qi, const ull* nQi,
                                      ull* Sr, ull* Sm, float xv)
{
    ull X2 = pack2(xv, xv);
#pragma unroll
    for (int j = 0; j < PACKS; j++) {
        ull t   = fma2(Qi[j], Sm[j], X2);
        ull nsr = fma2(Qr[j], Sr[j], t);
        ull nm  = fma2(nQi[j], Sr[j], mul2(Qr[j], Sm[j]));
        Sr[j] = nsr; Sm[j] = nm;
    }
}

// ---------------------------------------------------------------------------
// pass1: complex local scan, 1 thread per d, batches (b0, b0+1) merged.
// ---------------------------------------------------------------------------
__global__ void __launch_bounds__(128) s4d_pass1(
    const float* __restrict__ x, const float* __restrict__ log_dt,
    const float* __restrict__ log_A_real, const float* __restrict__ A_imag)
{
    int d  = blockIdx.x * 128 + threadIdx.x;
    int b0 = blockIdx.y * 2;
    int c  = blockIdx.z;

    float dt = __expf(log_dt[d]);

    ull Qr[PACKS], Qi[PACKS], nQi[PACKS];
    ull SrA[PACKS], SmA[PACKS], SrB[PACKS], SmB[PACKS];
#pragma unroll
    for (int j = 0; j < PACKS; j++) {
        float qr0, qi0, qr1, qi1;
        q_of(dt, log_A_real[d*NSTATE + 2*j],   A_imag[d*NSTATE + 2*j],   qr0, qi0);
        q_of(dt, log_A_real[d*NSTATE + 2*j+1], A_imag[d*NSTATE + 2*j+1], qr1, qi1);
        Qr[j]  = pack2(qr0, qr1);
        Qi[j]  = pack2(qi0, qi1);
        nQi[j] = pack2(-qi0, -qi1);
        SrA[j] = 0ull; SmA[j] = 0ull;
        SrB[j] = 0ull; SmB[j] = 0ull;
    }

    const float* xp = x + ((long long)(c * TCHUNK) * B_SZ + b0) * D_DIM + d;

    for (int it = 0; it < TCHUNK / 4; it++) {
        float a0 = xp[0];
        float b0v = xp[D_DIM];
        float a1 = xp[XS];
        float b1v = xp[XS + D_DIM];
        float a2 = xp[2 * XS];
        float b2v = xp[2 * XS + D_DIM];
        float a3 = xp[3 * XS];
        float b3v = xp[3 * XS + D_DIM];
        xp += 4 * XS;

        cstep(Qr, Qi, nQi, SrA, SmA, a0);
        cstep(Qr, Qi, nQi, SrB, SmB, b0v);
        cstep(Qr, Qi, nQi, SrA, SmA, a1);
        cstep(Qr, Qi, nQi, SrB, SmB, b1v);
        cstep(Qr, Qi, nQi, SrA, SmA, a2);
        cstep(Qr, Qi, nQi, SrB, SmB, b2v);
        cstep(Qr, Qi, nQi, SrA, SmA, a3);
        cstep(Qr, Qi, nQi, SrB, SmB, b3v);
    }

    float2* stA = g_state + (((long long)c * B_SZ + b0) * NSTATE) * D_DIM + d;
    float2* stB = stA + (long long)NSTATE * D_DIM;
#pragma unroll
    for (int j = 0; j < PACKS; j++) {
        float r0, r1, m0, m1;
        unpack2(SrA[j], r0, r1); unpack2(SmA[j], m0, m1);
        stA[(long long)(2*j    ) * D_DIM] = make_float2(r0, -m0);
        stA[(long long)(2*j + 1) * D_DIM] = make_float2(r1, -m1);
        unpack2(SrB[j], r0, r1); unpack2(SmB[j], m0, m1);
        stB[(long long)(2*j    ) * D_DIM] = make_float2(r0, -m0);
        stB[(long long)(2*j + 1) * D_DIM] = make_float2(r1, -m1);
    }
}

// ---------------------------------------------------------------------------
// pass2: carry propagation across chunks with q^TCHUNK
// ---------------------------------------------------------------------------
__global__ void s4d_pass2(
    const float* __restrict__ log_dt, const float* __restrict__ log_A_real,
    const float* __restrict__ A_imag)
{
    int id = blockIdx.x * blockDim.x + threadIdx.x;
    int total = B_SZ * NSTATE * D_DIM;
    if (id >= total) return;
    int d = id % D_DIM;
    int n = (id / D_DIM) % NSTATE;
    int b = id / (D_DIM * NSTATE);

    float dt = __expf(log_dt[d]);
    float qr, qi;
    q_of(dt, log_A_real[d * NSTATE + n], A_imag[d * NSTATE + n], qr, qi);

#pragma unroll
    for (int i = 0; i < LOG2_TCHUNK; i++) {
        float nr = qr * qr - qi * qi;
        float ni = 2.0f * qr * qi;
        qr = nr; qi = ni;
    }

    long long base    = ((long long)b * NSTATE + n) * D_DIM + d;
    long long cstride = (long long)B_SZ * NSTATE * D_DIM;
    float2 s = g_state[base];
    for (int c = 1; c < NCH; c++) {
        float2 t = g_state[base + (long long)c * cstride];
        float nr = qr * s.x - qi * s.y + t.x;
        float ni = qr * s.y + qi * s.x + t.y;
        s.x = nr; s.y = ni;
        g_state[base + (long long)c * cstride] = s;
    }
}

// ---------------------------------------------------------------------------
// pass3: 2nd-order real recurrence on u = Re(p*s), batches merged 2x.
// VD holds u_{i-2} on entry and receives u_i (role-alternating, no MOVs).
// ---------------------------------------------------------------------------
__device__ __forceinline__ float rstep(const ull* A, const ull* Bc,
                                       const ull* Pr, const ull* nG,
                                       const ull* V, ull* VD,
                                       float xc, float xm)
{
    ull Xc = pack2(xc, xc);
    ull Xm = pack2(xm, xm);
    ull acc0 = 0ull, acc1 = 0ull;
#pragma unroll
    for (int j = 0; j < PACKS; j++) {
        ull w  = fma2(Pr[j], Xc, mul2(nG[j], Xm));
        ull t  = fma2(Bc[j], VD[j], w);
        ull nv = fma2(A[j], V[j], t);
        VD[j] = nv;
        if (j & 1) acc1 = add2(acc1, nv);
        else       acc0 = add2(acc0, nv);
    }
    ull s = add2(acc0, acc1);
    float lo, hi; unpack2(s, lo, hi);
    return lo + hi;
}

__global__ void __launch_bounds__(128) s4d_pass3(
    const float* __restrict__ x, const float* __restrict__ log_dt,
    const float* __restrict__ log_A_real, const float* __restrict__ A_imag,
    const float* __restrict__ Bparam, const float* __restrict__ Cparam,
    const float* __restrict__ Dparam, float* __restrict__ out)
{
    int d  = blockIdx.x * 128 + threadIdx.x;
    int b0 = blockIdx.y * 2;
    int c  = blockIdx.z;

    float dt = __expf(log_dt[d]);

    const float* xp = x + ((long long)(c * TCHUNK) * B_SZ + b0) * D_DIM + d;
    float* op = out + ((long long)(c * TCHUNK) * B_SZ + b0) * D_DIM + d;
    float dpar = Dparam[d];

    float xa0 = xp[0];
    float xb0 = xp[D_DIM];

    ull A[PACKS], Bc[PACKS], Pr[PACKS], nG[PACKS];
    ull UA0[PACKS], UA1[PACKS], UB0[PACKS], UB1[PACKS];  // U*0 = u_0, U*1 = u_{-1}
    float y0A = 0.0f, y0B = 0.0f;

#pragma unroll
    for (int j = 0; j < PACKS; j++) {
        float aa[2], bb[2], prr[2], gg[2];
        float u0a[2], m1a[2], u0b[2], m1b[2];
#pragma unroll
        for (int k = 0; k < 2; k++) {
            int n = d * NSTATE + 2 * j + k;
            float zr = -0.5f * dt * __expf(log_A_real[n]);
            float zi =  0.5f * dt * A_imag[n];
            float omz = 1.0f - zr;
            float inv = __fdividef(1.0f, omz * omz + zi * zi);
            float qr = (1.0f - zr * zr - zi * zi) * inv;
            float qi = 2.0f * zi * inv;
            float Br = Bparam[n * 2 + 0];
            float Bi = Bparam[n * 2 + 1];
            float Cr = Cparam[n * 2 + 0];
            float Ci = Cparam[n * 2 + 1];
            float ccr = Br * Cr - Bi * Ci;
            float cci = Br * Ci + Bi * Cr;
            float w = dt * SCALE_F * inv;
            float pr = w * (ccr * omz - cci * zi);
            float pi = w * (ccr * zi + cci * omz);

            aa[k]  = 2.0f * qr;
            bb[k]  = -(qr * qr + qi * qi);
            prr[k] = pr;
            gg[k]  = -(pr * qr + pi * qi);

            float pqr = pr * qr - pi * qi;
            float pqi = pr * qi + pi * qr;

            float srA = 0.0f, siA = 0.0f, srB = 0.0f, siB = 0.0f;
            if (c > 0) {
                long long idx = (((long long)(c-1) * B_SZ + b0) * NSTATE + 2*j + k) * D_DIM + d;
                float2 vA = g_state[idx];
                float2 vB = g_state[idx + (long long)NSTATE * D_DIM];
                srA = vA.x; siA = vA.y; srB = vB.x; siB = vB.y;
            }
            m1a[k] = pr * srA - pi * siA;
            u0a[k] = pqr * srA - pqi * siA + pr * xa0;
            y0A += u0a[k];
            m1b[k] = pr * srB - pi * siB;
            u0b[k] = pqr * srB - pqi * siB + pr * xb0;
            y0B += u0b[k];
        }
        A[j]   = pack2(aa[0], aa[1]);
        Bc[j]  = pack2(bb[0], bb[1]);
        Pr[j]  = pack2(prr[0], prr[1]);
        nG[j]  = pack2(gg[0], gg[1]);
        UA0[j] = pack2(u0a[0], u0a[1]);
        UA1[j] = pack2(m1a[0], m1a[1]);
        UB0[j] = pack2(u0b[0], u0b[1]);
        UB1[j] = pack2(m1b[0], m1b[1]);
    }

    // output index 0
    op[0]     = silu_of(fmaf(xa0, dpar, y0A));
    op[D_DIM] = silu_of(fmaf(xb0, dpar, y0B));

    // step i = 1: result goes into U*1 (roles swap)
    float xmA = xa0, xmB = xb0;
    {
        float xcA = xp[XS];
        float xcB = xp[XS + D_DIM];
        float yA = rstep(A, Bc, Pr, nG, UA0, UA1, xcA, xmA);
        float yB = rstep(A, Bc, Pr, nG, UB0, UB1, xcB, xmB);
        op[XS]         = silu_of(fmaf(xcA, dpar, yA));
        op[XS + D_DIM] = silu_of(fmaf(xcB, dpar, yB));
        xmA = xcA; xmB = xcB;
    }

    // steps i = 2..127 in pairs; roles alternate (U*1 newest entering loop)
    const float* xq = xp + 2 * XS;
    float* oq = op + 2 * XS;
    for (int it = 0; it < (TCHUNK - 2) / 2; it++) {
        float a0  = xq[0];
        float b0v = xq[D_DIM];
        float a1  = xq[XS];
        float b1v = xq[XS + D_DIM];
        xq += 2 * XS;

        float yA0 = rstep(A, Bc, Pr, nG, UA1, UA0, a0, xmA);
        float yB0 = rstep(A, Bc, Pr, nG, UB1, UB0, b0v, xmB);
        float yA1 = rstep(A, Bc, Pr, nG, UA0, UA1, a1, a0);
        float yB1 = rstep(A, Bc, Pr, nG, UB0, UB1, b1v, b0v);

        oq[0]          = silu_of(fmaf(a0,  dpar, yA0));
        oq[D_DIM]      = silu_of(fmaf(b0v, dpar, yB0));
        oq[XS]         = silu_of(fmaf(a1,  dpar, yA1));
        oq[XS + D_DIM] = silu_of(fmaf(b1v, dpar, yB1));

        xmA = a1; xmB = b1v;
        oq += 2 * XS;
    }
}

extern "C" void kernel_launch(void* const* d_in, const int* in_sizes, int n_in,
                              void* d_out, int out_size)
{
    const float* x      = (const float*)d_in[0];
    const float* log_dt = (const float*)d_in[1];
    const float* lar    = (const float*)d_in[2];
    const float* aim    = (const float*)d_in[3];
    const float* Bp     = (const float*)d_in[4];
    const float* Cp     = (const float*)d_in[5];
    const float* Dp     = (const float*)d_in[6];
    float* out = (float*)d_out;

    dim3 blk(128);
    dim3 grd(D_DIM / 128, B_SZ / 2, NCH);   // (8, 2, 32) = 512 blocks

    s4d_pass1<<<grd, blk>>>(x, log_dt, lar, aim);

    int total2 = B_SZ * NSTATE * D_DIM;
    s4d_pass2<<<(total2 + 255) / 256, 256>>>(log_dt, lar, aim);

    s4d_pass3<<<grd, blk>>>(x, log_dt, lar, aim, Bp, Cp, Dp, out);
}

// round 6
// speedup vs baseline: 1.2302x; 1.1264x over previous
#include <cuda_runtime.h>

// S4D SSM layer, recurrence formulation of the FFT causal conv.
// Shapes hardcoded: L=4096, B=4, D=1024, N=16.
//
// pass1: complex local scan per chunk (zero init), 1 thread per d  [R2 shape]
// pass2: carry propagation across chunks, all 32 chunk states preloaded
// pass3: 2nd-order REAL recurrence on u = Re(p*s):
//        u_i = a u_{i-1} + b u_{i-2} + pr*x_i - g*x_{i-1}

#define NSTATE 16
#define PACKS  8
#define TCHUNK 128
#define LOG2_TCHUNK 7
#define NCH    32              // L / TCHUNK
#define D_DIM  1024
#define B_SZ   4
#define XS     (B_SZ * D_DIM)  // float stride per timestep = 4096
#define SCALE_F 0.25f

typedef unsigned long long ull;

__device__ __forceinline__ ull pack2(float lo, float hi) {
    ull r; asm("mov.b64 %0, {%1,%2};" : "=l"(r) : "f"(lo), "f"(hi)); return r;
}
__device__ __forceinline__ void unpack2(ull v, float& a, float& b) {
    asm("mov.b64 {%0,%1}, %2;" : "=f"(a), "=f"(b) : "l"(v));
}
__device__ __forceinline__ ull fma2(ull a, ull b, ull c) {
    ull d; asm("fma.rn.f32x2 %0, %1, %2, %3;" : "=l"(d) : "l"(a), "l"(b), "l"(c)); return d;
}
__device__ __forceinline__ ull mul2(ull a, ull b) {
    ull d; asm("mul.rn.f32x2 %0, %1, %2;" : "=l"(d) : "l"(a), "l"(b)); return d;
}
__device__ __forceinline__ ull add2(ull a, ull b) {
    ull d; asm("add.rn.f32x2 %0, %1, %2;" : "=l"(d) : "l"(a), "l"(b)); return d;
}

// chunk-boundary states: ((c*B + b)*NSTATE + n)*D + d  — coalesced in d
__device__ float2 g_state[1 << 21];   // 16 MB static scratch

__device__ __forceinline__ void q_of(float dt, float lar, float aim,
                                     float& qr, float& qi)
{
    float zr = -0.5f * dt * __expf(lar);
    float zi =  0.5f * dt * aim;
    float omz = 1.0f - zr;
    float inv = __fdividef(1.0f, omz * omz + zi * zi);
    qr = (1.0f - zr * zr - zi * zi) * inv;
    qi = 2.0f * zi * inv;
}

__device__ __forceinline__ float silu_of(float z) {
    float sg = __fdividef(1.0f, 1.0f + __expf(-z));
    return z * sg;
}

// ---------------------------------------------------------------------------
// pass1: complex local scan, 1 thread per d, x4 in-iteration loads (R2 shape)
// ---------------------------------------------------------------------------
__global__ void __launch_bounds__(128) s4d_pass1(
    const float* __restrict__ x, const float* __restrict__ log_dt,
    const float* __restrict__ log_A_real, const float* __restrict__ A_imag)
{
    int d = blockIdx.x * 128 + threadIdx.x;
    int b = blockIdx.y;
    int c = blockIdx.z;

    float dt = __expf(log_dt[d]);

    ull Qr[PACKS], Qi[PACKS], nQi[PACKS], Sr[PACKS], Sm[PACKS];
#pragma unroll
    for (int j = 0; j < PACKS; j++) {
        float qr0, qi0, qr1, qi1;
        q_of(dt, log_A_real[d*NSTATE + 2*j],   A_imag[d*NSTATE + 2*j],   qr0, qi0);
        q_of(dt, log_A_real[d*NSTATE + 2*j+1], A_imag[d*NSTATE + 2*j+1], qr1, qi1);
        Qr[j]  = pack2(qr0, qr1);
        Qi[j]  = pack2(qi0, qi1);
        nQi[j] = pack2(-qi0, -qi1);
        Sr[j] = 0ull; Sm[j] = 0ull;   // Sm holds m = -si
    }

    const float* xp = x + ((long long)(c * TCHUNK) * B_SZ + b) * D_DIM + d;

    for (int it = 0; it < TCHUNK / 4; it++) {
        float x0 = xp[0];
        float x1 = xp[XS];
        float x2 = xp[2 * XS];
        float x3 = xp[3 * XS];
        xp += 4 * XS;

#pragma unroll
        for (int u = 0; u < 4; u++) {
            float xv = (u == 0) ? x0 : (u == 1) ? x1 : (u == 2) ? x2 : x3;
            ull X2 = pack2(xv, xv);
#pragma unroll
            for (int j = 0; j < PACKS; j++) {
                ull t   = fma2(Qi[j], Sm[j], X2);
                ull nsr = fma2(Qr[j], Sr[j], t);
                ull nm  = fma2(nQi[j], Sr[j], mul2(Qr[j], Sm[j]));
                Sr[j] = nsr; Sm[j] = nm;
            }
        }
    }

    float2* st = g_state + (((long long)c * B_SZ + b) * NSTATE) * D_DIM + d;
#pragma unroll
    for (int j = 0; j < PACKS; j++) {
        float r0, r1, m0, m1;
        unpack2(Sr[j], r0, r1); unpack2(Sm[j], m0, m1);
        st[(long long)(2*j    ) * D_DIM] = make_float2(r0, -m0);
        st[(long long)(2*j + 1) * D_DIM] = make_float2(r1, -m1);
    }
}

// ---------------------------------------------------------------------------
// pass2: preload all 32 chunk states (MLP=32), scan in regs, store back.
// ---------------------------------------------------------------------------
__global__ void __launch_bounds__(256) s4d_pass2(
    const float* __restrict__ log_dt, const float* __restrict__ log_A_real,
    const float* __restrict__ A_imag)
{
    int id = blockIdx.x * 256 + threadIdx.x;
    int d = id % D_DIM;
    int n = (id / D_DIM) % NSTATE;
    int b = id / (D_DIM * NSTATE);

    float dt = __expf(log_dt[d]);
    float qr, qi;
    q_of(dt, log_A_real[d * NSTATE + n], A_imag[d * NSTATE + n], qr, qi);

#pragma unroll
    for (int i = 0; i < LOG2_TCHUNK; i++) {
        float nr = qr * qr - qi * qi;
        float ni = 2.0f * qr * qi;
        qr = nr; qi = ni;
    }

    long long base    = ((long long)b * NSTATE + n) * D_DIM + d;
    const long long cstride = (long long)B_SZ * NSTATE * D_DIM;

    float2 t[NCH];
#pragma unroll
    for (int c = 0; c < NCH; c++)
        t[c] = g_state[base + (long long)c * cstride];

    float2 s = t[0];
#pragma unroll
    for (int c = 1; c < NCH; c++) {
        float nr = fmaf(qr, s.x, fmaf(-qi, s.y, t[c].x));
        float ni = fmaf(qr, s.y, fmaf( qi, s.x, t[c].y));
        s.x = nr; s.y = ni;
        t[c] = s;
    }

#pragma unroll
    for (int c = 1; c < NCH; c++)
        g_state[base + (long long)c * cstride] = t[c];
}

// ---------------------------------------------------------------------------
// pass3: 2nd-order real recurrence on u = Re(p*s) + residual + silu.
// V = u_{i-1}, VD = u_{i-2} on entry; VD receives u_i (roles alternate).
// ---------------------------------------------------------------------------
__device__ __forceinline__ float rstep(const ull* A, const ull* Bc,
                                       const ull* Pr, const ull* nG,
                                       const ull* V, ull* VD,
                                       float xc, float xm)
{
    ull Xc = pack2(xc, xc);
    ull Xm = pack2(xm, xm);
    ull acc0 = 0ull, acc1 = 0ull;
#pragma unroll
    for (int j = 0; j < PACKS; j++) {
        ull w  = fma2(Pr[j], Xc, mul2(nG[j], Xm));
        ull t  = fma2(Bc[j], VD[j], w);
        ull nv = fma2(A[j], V[j], t);
        VD[j] = nv;
        if (j & 1) acc1 = add2(acc1, nv);
        else       acc0 = add2(acc0, nv);
    }
    ull s = add2(acc0, acc1);
    float lo, hi; unpack2(s, lo, hi);
    return lo + hi;
}

__global__ void __launch_bounds__(128) s4d_pass3(
    const float* __restrict__ x, const float* __restrict__ log_dt,
    const float* __restrict__ log_A_real, const float* __restrict__ A_imag,
    const float* __restrict__ Bparam, const float* __restrict__ Cparam,
    const float* __restrict__ Dparam, float* __restrict__ out)
{
    int d = blockIdx.x * 128 + threadIdx.x;
    int b = blockIdx.y;
    int c = blockIdx.z;

    float dt = __expf(log_dt[d]);
    const float* xp = x + ((long long)(c * TCHUNK) * B_SZ + b) * D_DIM + d;
    float* op = out + ((long long)(c * TCHUNK) * B_SZ + b) * D_DIM + d;
    float dpar = Dparam[d];

    float xs0 = xp[0];

    ull A[PACKS], Bc[PACKS], Pr[PACKS], nG[PACKS], U0[PACKS], U1[PACKS];
    float y0 = 0.0f;

#pragma unroll
    for (int j = 0; j < PACKS; j++) {
        float aa[2], bb[2], prr[2], gg[2], u0[2], um1[2];
#pragma unroll
        for (int k = 0; k < 2; k++) {
            int n = d * NSTATE + 2 * j + k;
            float zr = -0.5f * dt * __expf(log_A_real[n]);
            float zi =  0.5f * dt * A_imag[n];
            float omz = 1.0f - zr;
            float inv = __fdividef(1.0f, omz * omz + zi * zi);
            float qr = (1.0f - zr * zr - zi * zi) * inv;
            float qi = 2.0f * zi * inv;
            float Br = Bparam[n * 2 + 0];
            float Bi = Bparam[n * 2 + 1];
            float Cr = Cparam[n * 2 + 0];
            float Ci = Cparam[n * 2 + 1];
            float ccr = Br * Cr - Bi * Ci;
            float cci = Br * Ci + Bi * Cr;
            float w = dt * SCALE_F * inv;
            float pr = w * (ccr * omz - cci * zi);
            float pi = w * (ccr * zi + cci * omz);

            aa[k]  = 2.0f * qr;
            bb[k]  = -(qr * qr + qi * qi);
            prr[k] = pr;
            gg[k]  = -(pr * qr + pi * qi);

            float sr = 0.0f, si = 0.0f;
            if (c > 0) {
                float2 v = g_state[(((long long)(c-1) * B_SZ + b) * NSTATE + 2*j + k) * D_DIM + d];
                sr = v.x; si = v.y;
            }
            um1[k] = pr * sr - pi * si;                    // u_{-1} = Re(p s)
            float pqr = pr * qr - pi * qi;
            float pqi = pr * qi + pi * qr;
            u0[k]  = pqr * sr - pqi * si + pr * xs0;       // u_0
            y0 += u0[k];
        }
        A[j]  = pack2(aa[0], aa[1]);
        Bc[j] = pack2(bb[0], bb[1]);
        Pr[j] = pack2(prr[0], prr[1]);
        nG[j] = pack2(gg[0], gg[1]);
        U0[j] = pack2(u0[0], u0[1]);    // u_0 (newest)
        U1[j] = pack2(um1[0], um1[1]);  // u_{-1}
    }

    op[0] = silu_of(fmaf(xs0, dpar, y0));

    // step i = 1: V = U0 (u_0), VD = U1 (u_{-1}) -> U1 := u_1 (newest)
    float xm = xs0;
    {
        float xc = xp[XS];
        float y = rstep(A, Bc, Pr, nG, U0, U1, xc, xm);
        op[XS] = silu_of(fmaf(xc, dpar, y));
        xm = xc;
    }

    // steps i = 2..125: 31 iterations of 4 (parity restored each iteration;
    // entering each iteration U1 = newest, U0 = older)
    const float* xq = xp + 2 * XS;
    float* oq = op + 2 * XS;
    for (int it = 0; it < 31; it++) {
        float x0 = xq[0];
        float x1 = xq[XS];
        float x2 = xq[2 * XS];
        float x3 = xq[3 * XS];
        xq += 4 * XS;

        float y0v = rstep(A, Bc, Pr, nG, U1, U0, x0, xm);
        float y1v = rstep(A, Bc, Pr, nG, U0, U1, x1, x0);
        float y2v = rstep(A, Bc, Pr, nG, U1, U0, x2, x1);
        float y3v = rstep(A, Bc, Pr, nG, U0, U1, x3, x2);

        oq[0]      = silu_of(fmaf(x0, dpar, y0v));
        oq[XS]     = silu_of(fmaf(x1, dpar, y1v));
        oq[2 * XS] = silu_of(fmaf(x2, dpar, y2v));
        oq[3 * XS] = silu_of(fmaf(x3, dpar, y3v));

        xm = x3;
        oq += 4 * XS;
    }

    // tail steps i = 126, 127 (entering: U1 = newest)
    {
        float x0 = xq[0];
        float x1 = xq[XS];
        float ya = rstep(A, Bc, Pr, nG, U1, U0, x0, xm);
        float yb = rstep(A, Bc, Pr, nG, U0, U1, x1, x0);
        oq[0]  = silu_of(fmaf(x0, dpar, ya));
        oq[XS] = silu_of(fmaf(x1, dpar, yb));
    }
}

extern "C" void kernel_launch(void* const* d_in, const int* in_sizes, int n_in,
                              void* d_out, int out_size)
{
    const float* x      = (const float*)d_in[0];
    const float* log_dt = (const float*)d_in[1];
    const float* lar    = (const float*)d_in[2];
    const float* aim    = (const float*)d_in[3];
    const float* Bp     = (const float*)d_in[4];
    const float* Cp     = (const float*)d_in[5];
    const float* Dp     = (const float*)d_in[6];
    float* out = (float*)d_out;

    dim3 blk(128);
    dim3 grd(D_DIM / 128, B_SZ, NCH);   // (8, 4, 32) = 1024 blocks

    s4d_pass1<<<grd, blk>>>(x, log_dt, lar, aim);

    int total2 = B_SZ * NSTATE * D_DIM;      // 65536
    s4d_pass2<<<total2 / 256, 256>>>(log_dt, lar, aim);

    s4d_pass3<<<grd, blk>>>(x, log_dt, lar, aim, Bp, Cp, Dp, out);
}

// round 7
// speedup vs baseline: 1.2454x; 1.0124x over previous
#include <cuda_runtime.h>

// S4D SSM layer, recurrence formulation of the FFT causal conv.
// Shapes hardcoded: L=4096, B=4, D=1024, N=16.
//
// pass1: complex local scan per chunk (zero init), 1 thread per d, MLP=8
// pass2: carry propagation across chunks, all 32 chunk states in regs
// pass3: 2nd-order REAL recurrence on u = Re(p*s), MLP=8:
//        u_i = a u_{i-1} + b u_{i-2} + pr*x_i - g*x_{i-1}

#define NSTATE 16
#define PACKS  8
#define TCHUNK 128
#define LOG2_TCHUNK 7
#define NCH    32              // L / TCHUNK
#define D_DIM  1024
#define B_SZ   4
#define XS     (B_SZ * D_DIM)  // float stride per timestep = 4096
#define SCALE_F 0.25f

typedef unsigned long long ull;

__device__ __forceinline__ ull pack2(float lo, float hi) {
    ull r; asm("mov.b64 %0, {%1,%2};" : "=l"(r) : "f"(lo), "f"(hi)); return r;
}
__device__ __forceinline__ void unpack2(ull v, float& a, float& b) {
    asm("mov.b64 {%0,%1}, %2;" : "=f"(a), "=f"(b) : "l"(v));
}
__device__ __forceinline__ ull fma2(ull a, ull b, ull c) {
    ull d; asm("fma.rn.f32x2 %0, %1, %2, %3;" : "=l"(d) : "l"(a), "l"(b), "l"(c)); return d;
}
__device__ __forceinline__ ull mul2(ull a, ull b) {
    ull d; asm("mul.rn.f32x2 %0, %1, %2;" : "=l"(d) : "l"(a), "l"(b)); return d;
}
__device__ __forceinline__ ull add2(ull a, ull b) {
    ull d; asm("add.rn.f32x2 %0, %1, %2;" : "=l"(d) : "l"(a), "l"(b)); return d;
}

// chunk-boundary states: ((c*B + b)*NSTATE + n)*D + d  — coalesced in d
__device__ float2 g_state[1 << 21];   // 16 MB static scratch

__device__ __forceinline__ void q_of(float dt, float lar, float aim,
                                     float& qr, float& qi)
{
    float zr = -0.5f * dt * __expf(lar);
    float zi =  0.5f * dt * aim;
    float omz = 1.0f - zr;
    float inv = __fdividef(1.0f, omz * omz + zi * zi);
    qr = (1.0f - zr * zr - zi * zi) * inv;
    qi = 2.0f * zi * inv;
}

__device__ __forceinline__ float silu_of(float z) {
    float sg = __fdividef(1.0f, 1.0f + __expf(-z));
    return z * sg;
}

// ---------------------------------------------------------------------------
// pass1: complex local scan, 1 thread per d, 8 loads per iteration (MLP=8)
// ---------------------------------------------------------------------------
__global__ void __launch_bounds__(128) s4d_pass1(
    const float* __restrict__ x, const float* __restrict__ log_dt,
    const float* __restrict__ log_A_real, const float* __restrict__ A_imag)
{
    int d = blockIdx.x * 128 + threadIdx.x;
    int b = blockIdx.y;
    int c = blockIdx.z;

    float dt = __expf(log_dt[d]);

    ull Qr[PACKS], Qi[PACKS], nQi[PACKS], Sr[PACKS], Sm[PACKS];
#pragma unroll
    for (int j = 0; j < PACKS; j++) {
        float qr0, qi0, qr1, qi1;
        q_of(dt, log_A_real[d*NSTATE + 2*j],   A_imag[d*NSTATE + 2*j],   qr0, qi0);
        q_of(dt, log_A_real[d*NSTATE + 2*j+1], A_imag[d*NSTATE + 2*j+1], qr1, qi1);
        Qr[j]  = pack2(qr0, qr1);
        Qi[j]  = pack2(qi0, qi1);
        nQi[j] = pack2(-qi0, -qi1);
        Sr[j] = 0ull; Sm[j] = 0ull;   // Sm holds m = -si
    }

    const float* xp = x + ((long long)(c * TCHUNK) * B_SZ + b) * D_DIM + d;

    for (int it = 0; it < TCHUNK / 8; it++) {
        float xv[8];
#pragma unroll
        for (int u = 0; u < 8; u++)
            xv[u] = xp[(long long)u * XS];
        xp += 8 * XS;

#pragma unroll
        for (int u = 0; u < 8; u++) {
            ull X2 = pack2(xv[u], xv[u]);
#pragma unroll
            for (int j = 0; j < PACKS; j++) {
                ull t   = fma2(Qi[j], Sm[j], X2);
                ull nsr = fma2(Qr[j], Sr[j], t);
                ull nm  = fma2(nQi[j], Sr[j], mul2(Qr[j], Sm[j]));
                Sr[j] = nsr; Sm[j] = nm;
            }
        }
    }

    float2* st = g_state + (((long long)c * B_SZ + b) * NSTATE) * D_DIM + d;
#pragma unroll
    for (int j = 0; j < PACKS; j++) {
        float r0, r1, m0, m1;
        unpack2(Sr[j], r0, r1); unpack2(Sm[j], m0, m1);
        st[(long long)(2*j    ) * D_DIM] = make_float2(r0, -m0);
        st[(long long)(2*j + 1) * D_DIM] = make_float2(r1, -m1);
    }
}

// ---------------------------------------------------------------------------
// pass2: preload all 32 chunk states (MLP=32), scan in regs, store back.
// ---------------------------------------------------------------------------
__global__ void __launch_bounds__(256) s4d_pass2(
    const float* __restrict__ log_dt, const float* __restrict__ log_A_real,
    const float* __restrict__ A_imag)
{
    int id = blockIdx.x * 256 + threadIdx.x;
    int d = id % D_DIM;
    int n = (id / D_DIM) % NSTATE;
    int b = id / (D_DIM * NSTATE);

    float dt = __expf(log_dt[d]);
    float qr, qi;
    q_of(dt, log_A_real[d * NSTATE + n], A_imag[d * NSTATE + n], qr, qi);

#pragma unroll
    for (int i = 0; i < LOG2_TCHUNK; i++) {
        float nr = qr * qr - qi * qi;
        float ni = 2.0f * qr * qi;
        qr = nr; qi = ni;
    }

    long long base    = ((long long)b * NSTATE + n) * D_DIM + d;
    const long long cstride = (long long)B_SZ * NSTATE * D_DIM;

    float2 t[NCH];
#pragma unroll
    for (int c = 0; c < NCH; c++)
        t[c] = g_state[base + (long long)c * cstride];

    float2 s = t[0];
#pragma unroll
    for (int c = 1; c < NCH; c++) {
        float nr = fmaf(qr, s.x, fmaf(-qi, s.y, t[c].x));
        float ni = fmaf(qr, s.y, fmaf( qi, s.x, t[c].y));
        s.x = nr; s.y = ni;
        t[c] = s;
    }

#pragma unroll
    for (int c = 1; c < NCH; c++)
        g_state[base + (long long)c * cstride] = t[c];
}

// ---------------------------------------------------------------------------
// pass3: 2nd-order real recurrence on u = Re(p*s) + residual + silu.
// V = u_{i-1}, VD = u_{i-2} on entry; VD receives u_i (roles alternate).
// ---------------------------------------------------------------------------
__device__ __forceinline__ float rstep(const ull* A, const ull* Bc,
                                       const ull* Pr, const ull* nG,
                                       const ull* V, ull* VD,
                                       float xc, float xm)
{
    ull Xc = pack2(xc, xc);
    ull Xm = pack2(xm, xm);
    ull acc0 = 0ull, acc1 = 0ull;
#pragma unroll
    for (int j = 0; j < PACKS; j++) {
        ull w  = fma2(Pr[j], Xc, mul2(nG[j], Xm));
        ull t  = fma2(Bc[j], VD[j], w);
        ull nv = fma2(A[j], V[j], t);
        VD[j] = nv;
        if (j & 1) acc1 = add2(acc1, nv);
        else       acc0 = add2(acc0, nv);
    }
    ull s = add2(acc0, acc1);
    float lo, hi; unpack2(s, lo, hi);
    return lo + hi;
}

__global__ void __launch_bounds__(128) s4d_pass3(
    const float* __restrict__ x, const float* __restrict__ log_dt,
    const float* __restrict__ log_A_real, const float* __restrict__ A_imag,
    const float* __restrict__ Bparam, const float* __restrict__ Cparam,
    const float* __restrict__ Dparam, float* __restrict__ out)
{
    int d = blockIdx.x * 128 + threadIdx.x;
    int b = blockIdx.y;
    int c = blockIdx.z;

    float dt = __expf(log_dt[d]);
    const float* xp = x + ((long long)(c * TCHUNK) * B_SZ + b) * D_DIM + d;
    float* op = out + ((long long)(c * TCHUNK) * B_SZ + b) * D_DIM + d;
    float dpar = Dparam[d];

    float xs0 = xp[0];

    ull A[PACKS], Bc[PACKS], Pr[PACKS], nG[PACKS], U0[PACKS], U1[PACKS];
    float y0 = 0.0f;

#pragma unroll
    for (int j = 0; j < PACKS; j++) {
        float aa[2], bb[2], prr[2], gg[2], u0[2], um1[2];
#pragma unroll
        for (int k = 0; k < 2; k++) {
            int n = d * NSTATE + 2 * j + k;
            float zr = -0.5f * dt * __expf(log_A_real[n]);
            float zi =  0.5f * dt * A_imag[n];
            float omz = 1.0f - zr;
            float inv = __fdividef(1.0f, omz * omz + zi * zi);
            float qr = (1.0f - zr * zr - zi * zi) * inv;
            float qi = 2.0f * zi * inv;
            float Br = Bparam[n * 2 + 0];
            float Bi = Bparam[n * 2 + 1];
            float Cr = Cparam[n * 2 + 0];
            float Ci = Cparam[n * 2 + 1];
            float ccr = Br * Cr - Bi * Ci;
            float cci = Br * Ci + Bi * Cr;
            float w = dt * SCALE_F * inv;
            float pr = w * (ccr * omz - cci * zi);
            float pi = w * (ccr * zi + cci * omz);

            aa[k]  = 2.0f * qr;
            bb[k]  = -(qr * qr + qi * qi);
            prr[k] = pr;
            gg[k]  = -(pr * qr + pi * qi);

            float sr = 0.0f, si = 0.0f;
            if (c > 0) {
                float2 v = g_state[(((long long)(c-1) * B_SZ + b) * NSTATE + 2*j + k) * D_DIM + d];
                sr = v.x; si = v.y;
            }
            um1[k] = pr * sr - pi * si;                    // u_{-1} = Re(p s)
            float pqr = pr * qr - pi * qi;
            float pqi = pr * qi + pi * qr;
            u0[k]  = pqr * sr - pqi * si + pr * xs0;       // u_0
            y0 += u0[k];
        }
        A[j]  = pack2(aa[0], aa[1]);
        Bc[j] = pack2(bb[0], bb[1]);
        Pr[j] = pack2(prr[0], prr[1]);
        nG[j] = pack2(gg[0], gg[1]);
        U0[j] = pack2(u0[0], u0[1]);    // u_0 (newest)
        U1[j] = pack2(um1[0], um1[1]);  // u_{-1}
    }

    op[0] = silu_of(fmaf(xs0, dpar, y0));

    // step i = 1: V = U0 (u_0), VD = U1 (u_{-1}) -> U1 := u_1 (newest)
    float xm = xs0;
    {
        float xc = xp[XS];
        float y = rstep(A, Bc, Pr, nG, U0, U1, xc, xm);
        op[XS] = silu_of(fmaf(xc, dpar, y));
        xm = xc;
    }

    // steps i = 2..121: 15 blocks of 8 (entering each block U1 = newest)
    const float* xq = xp + 2 * XS;
    float* oq = op + 2 * XS;
    for (int it = 0; it < 15; it++) {
        float xv[8];
#pragma unroll
        for (int u = 0; u < 8; u++)
            xv[u] = xq[(long long)u * XS];
        xq += 8 * XS;

#pragma unroll
        for (int u = 0; u < 8; u++) {
            float prev = (u == 0) ? xm : xv[u - 1];
            float y = (u & 1) ? rstep(A, Bc, Pr, nG, U0, U1, xv[u], prev)
                              : rstep(A, Bc, Pr, nG, U1, U0, xv[u], prev);
            oq[(long long)u * XS] = silu_of(fmaf(xv[u], dpar, y));
        }
        xm = xv[7];
        oq += 8 * XS;
    }

    // tail steps i = 122..127 (6 steps, entering U1 = newest)
    {
        float xv[6];
#pragma unroll
        for (int u = 0; u < 6; u++)
            xv[u] = xq[(long long)u * XS];

#pragma unroll
        for (int u = 0; u < 6; u++) {
            float prev = (u == 0) ? xm : xv[u - 1];
            float y = (u & 1) ? rstep(A, Bc, Pr, nG, U0, U1, xv[u], prev)
                              : rstep(A, Bc, Pr, nG, U1, U0, xv[u], prev);
            oq[(long long)u * XS] = silu_of(fmaf(xv[u], dpar, y));
        }
    }
}

extern "C" void kernel_launch(void* const* d_in, const int* in_sizes, int n_in,
                              void* d_out, int out_size)
{
    const float* x      = (const float*)d_in[0];
    const float* log_dt = (const float*)d_in[1];
    const float* lar    = (const float*)d_in[2];
    const float* aim    = (const float*)d_in[3];
    const float* Bp     = (const float*)d_in[4];
    const float* Cp     = (const float*)d_in[5];
    const float* Dp     = (const float*)d_in[6];
    float* out = (float*)d_out;

    dim3 blk(128);
    dim3 grd(D_DIM / 128, B_SZ, NCH);   // (8, 4, 32) = 1024 blocks

    s4d_pass1<<<grd, blk>>>(x, log_dt, lar, aim);

    int total2 = B_SZ * NSTATE * D_DIM;      // 65536
    s4d_pass2<<<total2 / 256, 256>>>(log_dt, lar, aim);

    s4d_pass3<<<grd, blk>>>(x, log_dt, lar, aim, Bp, Cp, Dp, out);
}